// round 1
// baseline (speedup 1.0000x reference)
#include <cuda_runtime.h>

// ---------------------------------------------------------------------------
// DiscriminativeClueCorrection — fp32, algebraically restructured attention.
// Output layout (float32): [loss(1)] [corrected(512*512)] [cluster_scores(512*3)]
// ---------------------------------------------------------------------------

constexpr int kB    = 512;
constexpr int kM    = 96;
constexpr int kD    = 512;
constexpr int kH    = 8;
constexpr int kDH   = 64;
constexpr int kNC   = 3;
constexpr int kBeta = 5;
constexpr int kMem  = 1024;
constexpr int kNeg  = kB + kMem;   // 1536
constexpr float kEps = 1e-8f;

// ----- device scratch (static allocation; no cudaMalloc anywhere) -----------
__device__ float g_vn   [kB * kD];        // l2norm(vis_global)
__device__ float g_q    [kB * kD];        // q projection
__device__ float g_qt   [kB * kH * kD];   // q-transformed keys weight, pre-scaled 1/8
__device__ float g_qb   [kB * kH];        // q . bk, pre-scaled 1/8
__device__ float g_tctx [kB * kH * kD];   // attn-weighted text
__device__ float g_ctx  [kB * kD];
__device__ float g_cn   [kB * kD];        // l2norm(corrected)
__device__ float g_pos  [kB];
__device__ float g_negs [kNeg * kD];      // normalized negatives
__device__ float g_nsims[kB * kNeg];
__device__ float g_lossb[kB];

__device__ __forceinline__ float warp_sum(float v) {
#pragma unroll
    for (int o = 16; o > 0; o >>= 1) v += __shfl_xor_sync(0xffffffffu, v, o);
    return v;
}
__device__ __forceinline__ float warp_max(float v) {
#pragma unroll
    for (int o = 16; o > 0; o >>= 1) v = fmaxf(v, __shfl_xor_sync(0xffffffffu, v, o));
    return v;
}

// ----- normalize vis_global rows --------------------------------------------
__global__ void k_norm_vis(const float* __restrict__ vis) {
    int b = blockIdx.x, t = threadIdx.x;                 // 256 threads
    const float* x = vis + (size_t)b * kD;
    float ss = 0.f;
    for (int i = t; i < kD; i += 256) { float v = x[i]; ss += v * v; }
    __shared__ float red[8];
    ss = warp_sum(ss);
    if ((t & 31) == 0) red[t >> 5] = ss;
    __syncthreads();
    if (t < 32) {
        float v = (t < 8) ? red[t] : 0.f;
        v = warp_sum(v);
        if (t == 0) red[0] = v;
    }
    __syncthreads();
    float inv = 1.0f / fmaxf(sqrtf(red[0]), kEps);
    for (int i = t; i < kD; i += 256) g_vn[(size_t)b * kD + i] = x[i] * inv;
}

// ----- generic NT GEMM: C = A(MxK) @ B(NxK)^T + bias, 64x64 tile, BK=16 ------
__global__ void __launch_bounds__(256)
k_gemm_nt(const float* __restrict__ A, int lda, int sAz,
          const float* __restrict__ Bm, int ldb, int sBz,
          const float* __restrict__ bias, int sBiasz,
          float* __restrict__ C, int ldc, int sCz, int K) {
    A  += (size_t)blockIdx.z * sAz + (size_t)blockIdx.y * 64 * lda;
    Bm += (size_t)blockIdx.z * sBz + (size_t)blockIdx.x * 64 * ldb;
    C  += (size_t)blockIdx.z * sCz + (size_t)blockIdx.y * 64 * ldc + blockIdx.x * 64;
    int biasOff = blockIdx.z * sBiasz + blockIdx.x * 64;

    __shared__ float As[16][64];
    __shared__ float Bs[16][64];
    int tid = threadIdx.x;
    int tx = tid & 15, ty = tid >> 4;
    int lr = tid >> 2, lk = (tid & 3) << 2;

    float acc[4][4] = {};
    for (int k0 = 0; k0 < K; k0 += 16) {
        float4 a4 = *(const float4*)(A  + (size_t)lr * lda + k0 + lk);
        float4 b4 = *(const float4*)(Bm + (size_t)lr * ldb + k0 + lk);
        As[lk + 0][lr] = a4.x; As[lk + 1][lr] = a4.y; As[lk + 2][lr] = a4.z; As[lk + 3][lr] = a4.w;
        Bs[lk + 0][lr] = b4.x; Bs[lk + 1][lr] = b4.y; Bs[lk + 2][lr] = b4.z; Bs[lk + 3][lr] = b4.w;
        __syncthreads();
#pragma unroll
        for (int k = 0; k < 16; k++) {
            float4 av = *(const float4*)&As[k][ty << 2];
            float4 bv = *(const float4*)&Bs[k][tx << 2];
            float am[4] = {av.x, av.y, av.z, av.w};
            float bn[4] = {bv.x, bv.y, bv.z, bv.w};
#pragma unroll
            for (int i = 0; i < 4; i++)
#pragma unroll
                for (int j = 0; j < 4; j++) acc[i][j] += am[i] * bn[j];
        }
        __syncthreads();
    }
#pragma unroll
    for (int i = 0; i < 4; i++) {
        int row = (ty << 2) + i;
#pragma unroll
        for (int j = 0; j < 4; j++) {
            int col = (tx << 2) + j;
            float v = acc[i][j];
            if (bias) v += bias[biasOff + col];
            C[(size_t)row * ldc + col] = v;
        }
    }
}

// ----- qt[b,h,d] = (1/8) * sum_dh q[b,h,dh] * Wk[h*64+dh, d]  (NN, K=64) -----
__global__ void __launch_bounds__(256)
k_qt_kernel(const float* __restrict__ wk) {
    int h = blockIdx.z, b0 = blockIdx.y * 64, d0 = blockIdx.x * 64;
    __shared__ float Qs[64][64];   // [dh][b]
    __shared__ float Ws[64][64];   // [dh][d]
    int tid = threadIdx.x;

    {   // load Q tile (rows=b, cols=dh), store transposed into Qs[dh][b]
        int lr = tid >> 2, lk = (tid & 3) << 2;
        const float* qrow = g_q + (size_t)(b0 + lr) * kD + h * kDH;
#pragma unroll
        for (int c = 0; c < 4; c++) {
            float4 v = *(const float4*)(qrow + lk + c * 16);
            int cc = lk + c * 16;
            Qs[cc + 0][lr] = v.x; Qs[cc + 1][lr] = v.y; Qs[cc + 2][lr] = v.z; Qs[cc + 3][lr] = v.w;
        }
    }
    {   // load W tile (rows=dh, cols=d) straight
        int wr = tid >> 2, wc = (tid & 3) << 2;
        const float* wrow = wk + (size_t)(h * kDH + wr) * kD + d0;
#pragma unroll
        for (int c = 0; c < 4; c++)
            *(float4*)&Ws[wr][wc + c * 16] = *(const float4*)(wrow + wc + c * 16);
    }
    __syncthreads();

    int tx = tid & 15, ty = tid >> 4;
    float acc[4][4] = {};
#pragma unroll
    for (int k = 0; k < 64; k++) {
        float4 av = *(const float4*)&Qs[k][ty << 2];
        float4 bv = *(const float4*)&Ws[k][tx << 2];
        float am[4] = {av.x, av.y, av.z, av.w};
        float bn[4] = {bv.x, bv.y, bv.z, bv.w};
#pragma unroll
        for (int i = 0; i < 4; i++)
#pragma unroll
            for (int j = 0; j < 4; j++) acc[i][j] += am[i] * bn[j];
    }
#pragma unroll
    for (int i = 0; i < 4; i++)
#pragma unroll
        for (int j = 0; j < 4; j++)
            g_qt[(size_t)(b0 + (ty << 2) + i) * (kH * kD) + (size_t)h * kD + d0 + (tx << 2) + j]
                = 0.125f * acc[i][j];
}

// ----- qb[b,h] = (1/8) * sum_dh q[b,h,dh] * bk[h*64+dh] ----------------------
__global__ void k_qb(const float* __restrict__ bk) {
    int b = blockIdx.x, t = threadIdx.x;   // 256 threads = 8 warps = 8 heads
    int h = t >> 5, lane = t & 31;
    float s = 0.f;
    for (int i = lane; i < kDH; i += 32)
        s += g_q[(size_t)b * kD + h * kDH + i] * bk[h * kDH + i];
    s = warp_sum(s);
    if (lane == 0) g_qb[b * kH + h] = 0.125f * s;
}

// ----- fused per-b kernel: sims + sort/cluster + logits + softmax + tctx -----
__global__ void __launch_bounds__(512)
k_fused(const float* __restrict__ text, float* __restrict__ out_cs) {
    extern __shared__ float st[];                       // 96*512 floats (text[b])
    __shared__ float sims[128];
    __shared__ __align__(16) float attn2[kM][kH];       // [m][h]
    int b = blockIdx.x, t = threadIdx.x;
    int w = t >> 5, lane = t & 31;

    {   // stage text[b] into smem
        const float4* src = (const float4*)(text + (size_t)b * kM * kD);
        float4* dst = (float4*)st;
        for (int i = t; i < kM * kD / 4; i += 512) dst[i] = src[i];
    }
    __syncthreads();

    // sims[m] = vn[b] . (t_m / max(||t_m||, eps))
    const float* vnb = g_vn + (size_t)b * kD;
    for (int m = w; m < kM; m += 16) {
        const float* row = st + m * kD;
        float dot = 0.f, ss = 0.f;
        for (int i = lane; i < kD; i += 32) { float tv = row[i]; dot += vnb[i] * tv; ss += tv * tv; }
        dot = warp_sum(dot); ss = warp_sum(ss);
        if (lane == 0) sims[m] = dot / fmaxf(sqrtf(ss), kEps);
    }
    if (t >= kM && t < 128) sims[t] = -1e30f;
    __syncthreads();

    // bitonic ascending sort of sims[128] (-1e30 pads sort to the front)
    for (int k = 2; k <= 128; k <<= 1)
        for (int j = k >> 1; j > 0; j >>= 1) {
            if (t < 128) {
                int ixj = t ^ j;
                if (ixj > t) {
                    float a = sims[t], c = sims[ixj];
                    bool up = ((t & k) == 0);
                    if ((a > c) == up) { sims[t] = c; sims[ixj] = a; }
                }
            }
            __syncthreads();
        }

    // cluster stats on descending groups of 32 (warps 0..2)
    if (t < kM) {
        float v = sims[127 - t];                // descending rank t
        float mean = warp_sum(v) * (1.0f / 32.0f);
        float dv = v - mean;
        float var = warp_sum(dv * dv) * (1.0f / 31.0f);
        if (lane == 0) out_cs[b * kNC + (t >> 5)] = mean / (sqrtf(var) + 1e-6f);
    }

    // logits[m][h] = (text_m . qt[b,h]) + qb[b,h]   (scale 1/8 already folded)
    const float* qtb = g_qt + (size_t)b * kH * kD;
    for (int task = w; task < kM * kH; task += 16) {
        int m = task >> 3, h = task & 7;
        const float* row = st + m * kD;
        const float* qr = qtb + h * kD;
        float lg = 0.f;
        for (int i = lane; i < kD; i += 32) lg += qr[i] * row[i];
        lg = warp_sum(lg);
        if (lane == 0) attn2[m][h] = lg + g_qb[b * kH + h];
    }
    __syncthreads();

    // softmax over m per head (warps 0..7)
    if (t < 256) {
        int h = w;
        float v0 = attn2[lane][h], v1 = attn2[lane + 32][h], v2 = attn2[lane + 64][h];
        float mx = warp_max(fmaxf(v0, fmaxf(v1, v2)));
        v0 = expf(v0 - mx); v1 = expf(v1 - mx); v2 = expf(v2 - mx);
        float inv = 1.0f / warp_sum(v0 + v1 + v2);
        attn2[lane][h] = v0 * inv; attn2[lane + 32][h] = v1 * inv; attn2[lane + 64][h] = v2 * inv;
    }
    __syncthreads();

    // tctx[h, d=t] = sum_m attn[h][m] * text[m][d] ; each thread owns one d, all 8 h
    float acc[8] = {0.f, 0.f, 0.f, 0.f, 0.f, 0.f, 0.f, 0.f};
#pragma unroll 4
    for (int m = 0; m < kM; m++) {
        float tv = st[m * kD + t];
        float4 a0 = *(const float4*)&attn2[m][0];
        float4 a1 = *(const float4*)&attn2[m][4];
        acc[0] += a0.x * tv; acc[1] += a0.y * tv; acc[2] += a0.z * tv; acc[3] += a0.w * tv;
        acc[4] += a1.x * tv; acc[5] += a1.y * tv; acc[6] += a1.z * tv; acc[7] += a1.w * tv;
    }
    float* tb = g_tctx + (size_t)b * kH * kD + t;
#pragma unroll
    for (int h = 0; h < kH; h++) tb[(size_t)h * kD] = acc[h];
}

// ----- normalize corrected rows + pos_sim ------------------------------------
__global__ void k_cn_pos(const float* __restrict__ corr) {
    int b = blockIdx.x, t = threadIdx.x;  // 256
    const float* x = corr + (size_t)b * kD;
    const float* vnb = g_vn + (size_t)b * kD;
    float ss = 0.f, dt = 0.f;
    for (int i = t; i < kD; i += 256) { float v = x[i]; ss += v * v; dt += vnb[i] * v; }
    __shared__ float rs[8], rd[8];
    ss = warp_sum(ss); dt = warp_sum(dt);
    if ((t & 31) == 0) { rs[t >> 5] = ss; rd[t >> 5] = dt; }
    __syncthreads();
    if (t < 32) {
        float s2 = (t < 8) ? rs[t] : 0.f;
        float d2 = (t < 8) ? rd[t] : 0.f;
        s2 = warp_sum(s2); d2 = warp_sum(d2);
        if (t == 0) { float inv = 1.0f / fmaxf(sqrtf(s2), kEps); rs[0] = inv; g_pos[b] = d2 * inv; }
    }
    __syncthreads();
    float inv = rs[0];
    for (int i = t; i < kD; i += 256) g_cn[(size_t)b * kD + i] = x[i] * inv;
}

// ----- build normalized negatives (1536 rows) --------------------------------
__global__ void k_negs(const float* __restrict__ tmem) {
    int j = blockIdx.x, t = threadIdx.x;  // 128 threads
    float* out = g_negs + (size_t)j * kD;
    if (j < 2 * kB) {
        int src = (j < kB) ? ((j + kB - 1) & (kB - 1)) : (j - kB);
        const float* x = g_cn + (size_t)src * kD;
        for (int i = t; i < kD; i += 128) out[i] = x[i];
    } else {
        const float* x = tmem + (size_t)(j - kB) * kD;   // rows 512..1023 of text_memory
        float ss = 0.f;
        for (int i = t; i < kD; i += 128) { float v = x[i]; ss += v * v; }
        __shared__ float red[4];
        ss = warp_sum(ss);
        if ((t & 31) == 0) red[t >> 5] = ss;
        __syncthreads();
        float tot = red[0] + red[1] + red[2] + red[3];
        float inv = 1.0f / fmaxf(sqrtf(tot), kEps);
        for (int i = t; i < kD; i += 128) out[i] = x[i] * inv;
    }
}

// ----- per-row top-5 + loss term ---------------------------------------------
__global__ void __launch_bounds__(256)
k_loss(const float* __restrict__ tpl, const float* __restrict__ tnl) {
    int b = blockIdx.x, t = threadIdx.x;
    __shared__ float buf[kNeg];
    __shared__ float rv[256];
    __shared__ int   ri[256];
    __shared__ float tops[kBeta];
    for (int i = t; i < kNeg; i += 256) buf[i] = g_nsims[(size_t)b * kNeg + i];
    __syncthreads();
    for (int it = 0; it < kBeta; it++) {
        float best = -1e30f; int bi = 0;
        for (int i = t; i < kNeg; i += 256)
            if (buf[i] > best) { best = buf[i]; bi = i; }
        rv[t] = best; ri[t] = bi;
        __syncthreads();
        for (int s = 128; s > 0; s >>= 1) {
            if (t < s && rv[t + s] > rv[t]) { rv[t] = rv[t + s]; ri[t] = ri[t + s]; }
            __syncthreads();
        }
        if (t == 0) { tops[it] = rv[0]; buf[ri[0]] = -1e30f; }
        __syncthreads();
    }
    if (t == 0) {
        float tau_p = expf(tpl[0]), tau_n = expf(tnl[0]);
        float pos = expf(g_pos[b] / tau_p);
        float neg = 0.f;
#pragma unroll
        for (int i = 0; i < kBeta; i++) neg += expf(tops[i] / tau_n);
        g_lossb[b] = logf(pos / (pos + neg + 1e-8f));
    }
}

__global__ void k_final(float* __restrict__ out) {
    int t = threadIdx.x;  // 512
    float v = g_lossb[t];
    __shared__ float red[16];
    v = warp_sum(v);
    if ((t & 31) == 0) red[t >> 5] = v;
    __syncthreads();
    if (t < 32) {
        float s = (t < 16) ? red[t] : 0.f;
        s = warp_sum(s);
        if (t == 0) out[0] = -s / (float)kB;
    }
}

// ---------------------------------------------------------------------------
extern "C" void kernel_launch(void* const* d_in, const int* in_sizes, int n_in,
                              void* d_out, int out_size) {
    const float* vis  = (const float*)d_in[0];
    const float* text = (const float*)d_in[1];
    const float* ipw  = (const float*)d_in[2];
    const float* ipb  = (const float*)d_in[3];
    const float* opw  = (const float*)d_in[4];
    const float* opb  = (const float*)d_in[5];
    const float* tmem = (const float*)d_in[6];
    const float* tpl  = (const float*)d_in[7];
    const float* tnl  = (const float*)d_in[8];

    float* out      = (float*)d_out;
    float* out_corr = out + 1;
    float* out_cs   = out + 1 + kB * kD;

    float *p_q, *p_vn, *p_tctx, *p_ctx, *p_negs, *p_nsims;
    cudaGetSymbolAddress((void**)&p_q,     g_q);
    cudaGetSymbolAddress((void**)&p_vn,    g_vn);
    cudaGetSymbolAddress((void**)&p_tctx,  g_tctx);
    cudaGetSymbolAddress((void**)&p_ctx,   g_ctx);
    cudaGetSymbolAddress((void**)&p_negs,  g_negs);
    cudaGetSymbolAddress((void**)&p_nsims, g_nsims);

    const int fusedSmem = kM * kD * (int)sizeof(float);   // 196608 B
    cudaFuncSetAttribute(k_fused, cudaFuncAttributeMaxDynamicSharedMemorySize, fusedSmem);

    // 1. normalize vis
    k_norm_vis<<<kB, 256>>>(vis);
    // 2. q = vis @ Wq^T + bq
    k_gemm_nt<<<dim3(kD / 64, kB / 64, 1), 256>>>(vis, kD, 0, ipw, kD, 0, ipb, 0,
                                                  p_q, kD, 0, kD);
    // 3. qt = (1/8) q_h @ Wk_h   (per head)
    k_qt_kernel<<<dim3(kD / 64, kB / 64, kH), 256>>>(ipw + (size_t)kD * kD);
    // 4. qb = (1/8) q_h . bk_h
    k_qb<<<kB, 256>>>(ipb + kD);
    // 5. fused: sims + clustering + logits + softmax + tctx
    k_fused<<<kB, 512, fusedSmem>>>(text, out_cs);
    // 6. ctx_h = tctx_h @ Wv_h^T + bv_h   (block-diagonal, grid.z = head)
    k_gemm_nt<<<dim3(1, kB / 64, kH), 256>>>(p_tctx, kH * kD, kD,
                                             ipw + 2 * (size_t)kD * kD, kD, kDH * kD,
                                             ipb + 2 * kD, kDH,
                                             p_ctx, kD, kDH, kD);
    // 7. corrected = ctx @ Wo^T + bo  -> straight into d_out
    k_gemm_nt<<<dim3(kD / 64, kB / 64, 1), 256>>>(p_ctx, kD, 0, opw, kD, 0, opb, 0,
                                                  out_corr, kD, 0, kD);
    // 8. normalize corrected + pos_sim
    k_cn_pos<<<kB, 256>>>(out_corr);
    // 9. build normalized negatives
    k_negs<<<kNeg, 128>>>(tmem);
    // 10. neg_sims = vn @ negs^T
    k_gemm_nt<<<dim3(kNeg / 64, kB / 64, 1), 256>>>(p_vn, kD, 0, p_negs, kD, 0,
                                                    nullptr, 0, p_nsims, kNeg, 0, kD);
    // 11. top-5 + per-row loss
    k_loss<<<kB, 256>>>(tpl, tnl);
    // 12. mean reduce -> loss scalar
    k_final<<<1, 512>>>(out);
}

// round 3
// speedup vs baseline: 1.1216x; 1.1216x over previous
#include <cuda_runtime.h>

// ---------------------------------------------------------------------------
// DiscriminativeClueCorrection — fp32 + FFMA2 (f32x2) GEMMs, restructured.
// Output layout (float32): [loss(1)] [corrected(512*512)] [cluster_scores(512*3)]
// ---------------------------------------------------------------------------

constexpr int kB    = 512;
constexpr int kM    = 96;
constexpr int kD    = 512;
constexpr int kH    = 8;
constexpr int kDH   = 64;
constexpr int kNC   = 3;
constexpr int kNegC = 1024;         // unique negative columns (cn ×512 + mem ×512)
constexpr float kEps = 1e-8f;

// ----- device scratch --------------------------------------------------------
__device__ float g_vn   [kB * kD];        // l2norm(vis_global)
__device__ float g_q    [kB * kD];        // q projection
__device__ float g_qt   [kB * kH * kD];   // per-b transformed key weights (×1/8)
__device__ float g_tctx [kB * kH * kD];   // attn-weighted text
__device__ float g_ctx  [kB * kD];
__device__ float g_corr [kB * kD];        // aligned copy of corrected
__device__ float g_pos  [kB];
__device__ float g_negs [kNegC * kD];     // [0:512) l2norm(corrected), [512:1024) l2norm(mem[512:1024])
__device__ float g_nsims[kB * kNegC];
__device__ float g_lossb[kB];

__device__ __forceinline__ float warp_sum(float v) {
#pragma unroll
    for (int o = 16; o > 0; o >>= 1) v += __shfl_xor_sync(0xffffffffu, v, o);
    return v;
}
__device__ __forceinline__ float warp_max(float v) {
#pragma unroll
    for (int o = 16; o > 0; o >>= 1) v = fmaxf(v, __shfl_xor_sync(0xffffffffu, v, o));
    return v;
}

// ----- f32x2 packed helpers ---------------------------------------------------
__device__ __forceinline__ unsigned long long dup2(float v) {
    unsigned long long r;
    asm("mov.b64 %0, {%1,%1};" : "=l"(r) : "f"(v));
    return r;
}
__device__ __forceinline__ void fma2(unsigned long long& acc, unsigned long long a,
                                     unsigned long long b) {
    asm("fma.rn.f32x2 %0, %1, %2, %0;" : "+l"(acc) : "l"(a), "l"(b));
}
__device__ __forceinline__ float2 unpack2(unsigned long long v) {
    float2 f;
    asm("mov.b64 {%0,%1}, %2;" : "=f"(f.x), "=f"(f.y) : "l"(v));
    return f;
}

// ----- normalize vis_global rows ----------------------------------------------
__global__ void k_norm_vis(const float* __restrict__ vis) {
    int b = blockIdx.x, t = threadIdx.x;                 // 256 threads
    const float* x = vis + (size_t)b * kD;
    float ss = 0.f;
    for (int i = t; i < kD; i += 256) { float v = x[i]; ss += v * v; }
    __shared__ float red[8];
    ss = warp_sum(ss);
    if ((t & 31) == 0) red[t >> 5] = ss;
    __syncthreads();
    if (t < 32) {
        float v = (t < 8) ? red[t] : 0.f;
        v = warp_sum(v);
        if (t == 0) red[0] = v;
    }
    __syncthreads();
    float inv = 1.0f / fmaxf(sqrtf(red[0]), kEps);
    for (int i = t; i < kD; i += 256) g_vn[(size_t)b * kD + i] = x[i] * inv;
}

// ----- NT GEMM with FFMA2: C = A(MxK) @ B(NxK)^T + bias, 64x64 tile, BK=16 ----
__global__ void __launch_bounds__(256)
k_gemm_nt(const float* __restrict__ A, int lda, int sAz,
          const float* __restrict__ Bm, int ldb, int sBz,
          const float* __restrict__ bias, int sBiasz,
          float* __restrict__ C, int ldc, int sCz, int K) {
    A  += (size_t)blockIdx.z * sAz + (size_t)blockIdx.y * 64 * lda;
    Bm += (size_t)blockIdx.z * sBz + (size_t)blockIdx.x * 64 * ldb;
    C  += (size_t)blockIdx.z * sCz + (size_t)blockIdx.y * 64 * ldc + blockIdx.x * 64;
    int biasOff = blockIdx.z * sBiasz + blockIdx.x * 64;

    __shared__ __align__(16) float As2[16][128];   // A duplicated: [k][2r],[k][2r+1]
    __shared__ __align__(16) float Bs[16][64];
    int tid = threadIdx.x;
    int tx = tid & 15, ty = tid >> 4;
    int lr = tid >> 2, lk = (tid & 3) << 2;

    const float* Aload = A + (size_t)lr * lda + lk;
    const float* Bload = Bm + (size_t)lr * ldb + lk;
    float4 a4 = *(const float4*)Aload;
    float4 b4 = *(const float4*)Bload;

    unsigned long long acc[4][2] = {};
    for (int k0 = 0; k0 < K; k0 += 16) {
        *(unsigned long long*)&As2[lk + 0][2 * lr] = dup2(a4.x);
        *(unsigned long long*)&As2[lk + 1][2 * lr] = dup2(a4.y);
        *(unsigned long long*)&As2[lk + 2][2 * lr] = dup2(a4.z);
        *(unsigned long long*)&As2[lk + 3][2 * lr] = dup2(a4.w);
        Bs[lk + 0][lr] = b4.x; Bs[lk + 1][lr] = b4.y;
        Bs[lk + 2][lr] = b4.z; Bs[lk + 3][lr] = b4.w;
        __syncthreads();
        if (k0 + 16 < K) {
            a4 = *(const float4*)(Aload + k0 + 16);
            b4 = *(const float4*)(Bload + k0 + 16);
        }
#pragma unroll
        for (int k = 0; k < 16; k++) {
            ulonglong2 ap0 = *(const ulonglong2*)&As2[k][ty * 8];
            ulonglong2 ap1 = *(const ulonglong2*)&As2[k][ty * 8 + 4];
            ulonglong2 bp  = *(const ulonglong2*)&Bs[k][tx * 4];
            fma2(acc[0][0], ap0.x, bp.x); fma2(acc[0][1], ap0.x, bp.y);
            fma2(acc[1][0], ap0.y, bp.x); fma2(acc[1][1], ap0.y, bp.y);
            fma2(acc[2][0], ap1.x, bp.x); fma2(acc[2][1], ap1.x, bp.y);
            fma2(acc[3][0], ap1.y, bp.x); fma2(acc[3][1], ap1.y, bp.y);
        }
        __syncthreads();
    }
#pragma unroll
    for (int i = 0; i < 4; i++) {
        int row = ty * 4 + i;
        int col = tx * 4;
        float2 c0 = unpack2(acc[i][0]);
        float2 c1 = unpack2(acc[i][1]);
        float4 v = make_float4(c0.x, c0.y, c1.x, c1.y);
        if (bias) {
            v.x += bias[biasOff + col + 0]; v.y += bias[biasOff + col + 1];
            v.z += bias[biasOff + col + 2]; v.w += bias[biasOff + col + 3];
        }
        *(float4*)&C[(size_t)row * ldc + col] = v;
    }
}

// ----- qt[b,h,d] = (1/8) * sum_dh q[b,h,dh] * Wk[h*64+dh, d]  (NN, K=64) ------
__global__ void __launch_bounds__(256)
k_qt_kernel(const float* __restrict__ wk) {
    int h = blockIdx.z, b0 = blockIdx.y * 64, d0 = blockIdx.x * 64;
    __shared__ __align__(16) float Qs2[64][128];   // [dh][2b] duplicated
    __shared__ __align__(16) float Ws[64][64];     // [dh][d], pre-scaled by 1/8
    int tid = threadIdx.x;

    {   // load Q tile (rows=b, cols=dh), store transposed+duplicated
        int lr = tid >> 2, lk = (tid & 3) << 2;
        const float* qrow = g_q + (size_t)(b0 + lr) * kD + h * kDH;
#pragma unroll
        for (int c = 0; c < 4; c++) {
            float4 v = *(const float4*)(qrow + lk + c * 16);
            int cc = lk + c * 16;
            *(unsigned long long*)&Qs2[cc + 0][2 * lr] = dup2(v.x);
            *(unsigned long long*)&Qs2[cc + 1][2 * lr] = dup2(v.y);
            *(unsigned long long*)&Qs2[cc + 2][2 * lr] = dup2(v.z);
            *(unsigned long long*)&Qs2[cc + 3][2 * lr] = dup2(v.w);
        }
    }
    {   // load W tile (rows=dh, cols=d), fold in 1/8
        int wr = tid >> 2, wc = (tid & 3) << 2;
        const float* wrow = wk + (size_t)(h * kDH + wr) * kD + d0;
#pragma unroll
        for (int c = 0; c < 4; c++) {
            float4 v = *(const float4*)(wrow + wc + c * 16);
            v.x *= 0.125f; v.y *= 0.125f; v.z *= 0.125f; v.w *= 0.125f;
            *(float4*)&Ws[wr][wc + c * 16] = v;
        }
    }
    __syncthreads();

    int tx = tid & 15, ty = tid >> 4;
    unsigned long long acc[4][2] = {};
#pragma unroll 8
    for (int k = 0; k < 64; k++) {
        ulonglong2 ap0 = *(const ulonglong2*)&Qs2[k][ty * 8];
        ulonglong2 ap1 = *(const ulonglong2*)&Qs2[k][ty * 8 + 4];
        ulonglong2 bp  = *(const ulonglong2*)&Ws[k][tx * 4];
        fma2(acc[0][0], ap0.x, bp.x); fma2(acc[0][1], ap0.x, bp.y);
        fma2(acc[1][0], ap0.y, bp.x); fma2(acc[1][1], ap0.y, bp.y);
        fma2(acc[2][0], ap1.x, bp.x); fma2(acc[2][1], ap1.x, bp.y);
        fma2(acc[3][0], ap1.y, bp.x); fma2(acc[3][1], ap1.y, bp.y);
    }
#pragma unroll
    for (int i = 0; i < 4; i++) {
        float2 c0 = unpack2(acc[i][0]);
        float2 c1 = unpack2(acc[i][1]);
        float4 v = make_float4(c0.x, c0.y, c1.x, c1.y);
        *(float4*)&g_qt[(size_t)(b0 + ty * 4 + i) * (kH * kD) + (size_t)h * kD + d0 + tx * 4] = v;
    }
}

// ----- fused per-b: qb + sims + sort/cluster + logits + softmax + tctx --------
__global__ void __launch_bounds__(512)
k_fused(const float* __restrict__ text, const float* __restrict__ bk,
        float* __restrict__ out_cs) {
    extern __shared__ float dyn[];
    float* st  = dyn;                   // 96*512
    float* qts = dyn + kM * kD;         // 8*512
    float* vns = qts + kH * kD;         // 512
    __shared__ float sims[128];
    __shared__ __align__(16) float attn2[kM][kH];
    __shared__ float qbs[kH];
    int b = blockIdx.x, t = threadIdx.x;
    int w = t >> 5, lane = t & 31;

    {   // stage text[b], qt[b], vn[b]
        const float4* src = (const float4*)(text + (size_t)b * kM * kD);
        float4* dst = (float4*)st;
        for (int i = t; i < kM * kD / 4; i += 512) dst[i] = src[i];
        const float4* qsrc = (const float4*)(g_qt + (size_t)b * kH * kD);
        float4* qdst = (float4*)qts;
        for (int i = t; i < kH * kD / 4; i += 512) qdst[i] = qsrc[i];
        if (t < 128) ((float4*)vns)[t] = ((const float4*)(g_vn + (size_t)b * kD))[t];
    }
    if (w < 8) {   // qb[h] = (1/8) q[b,h] . bk_h
        float s = g_q[(size_t)b * kD + w * 64 + lane]       * bk[w * 64 + lane]
                + g_q[(size_t)b * kD + w * 64 + lane + 32]  * bk[w * 64 + lane + 32];
        s = warp_sum(s);
        if (lane == 0) qbs[w] = 0.125f * s;
    }
    __syncthreads();

    // sims[m] = vn[b] . l2norm(text_m)
    for (int m = w; m < kM; m += 16) {
        const float* row = st + m * kD;
        float dot = 0.f, ss = 0.f;
        for (int i = lane; i < kD; i += 32) { float tv = row[i]; dot += vns[i] * tv; ss += tv * tv; }
        dot = warp_sum(dot); ss = warp_sum(ss);
        if (lane == 0) sims[m] = dot / fmaxf(sqrtf(ss), kEps);
    }
    if (t >= kM && t < 128) sims[t] = -1e30f;
    __syncthreads();

    // bitonic ascending sort of sims[128]
    for (int k = 2; k <= 128; k <<= 1)
        for (int j = k >> 1; j > 0; j >>= 1) {
            if (t < 128) {
                int ixj = t ^ j;
                if (ixj > t) {
                    float a = sims[t], c = sims[ixj];
                    bool up = ((t & k) == 0);
                    if ((a > c) == up) { sims[t] = c; sims[ixj] = a; }
                }
            }
            __syncthreads();
        }

    // cluster stats on descending groups of 32 (warps 0..2)
    if (t < kM) {
        float v = sims[127 - t];
        float mean = warp_sum(v) * (1.0f / 32.0f);
        float dv = v - mean;
        float var = warp_sum(dv * dv) * (1.0f / 31.0f);
        if (lane == 0) out_cs[b * kNC + (t >> 5)] = mean / (sqrtf(var) + 1e-6f);
    }

    // logits: 2 passes × 4 heads, qt slice held in registers
#pragma unroll 1
    for (int pass = 0; pass < 2; pass++) {
        float qa0[16], qa1[16], qa2[16], qa3[16];
        const float* q0 = qts + (pass * 4 + 0) * kD + lane;
        const float* q1 = qts + (pass * 4 + 1) * kD + lane;
        const float* q2 = qts + (pass * 4 + 2) * kD + lane;
        const float* q3 = qts + (pass * 4 + 3) * kD + lane;
#pragma unroll
        for (int kk = 0; kk < 16; kk++) {
            qa0[kk] = q0[32 * kk]; qa1[kk] = q1[32 * kk];
            qa2[kk] = q2[32 * kk]; qa3[kk] = q3[32 * kk];
        }
        for (int m = w; m < kM; m += 16) {
            const float* row = st + m * kD + lane;
            float a0 = 0.f, a1 = 0.f, a2 = 0.f, a3 = 0.f;
#pragma unroll
            for (int kk = 0; kk < 16; kk++) {
                float tv = row[32 * kk];
                a0 += qa0[kk] * tv; a1 += qa1[kk] * tv;
                a2 += qa2[kk] * tv; a3 += qa3[kk] * tv;
            }
            a0 = warp_sum(a0); a1 = warp_sum(a1); a2 = warp_sum(a2); a3 = warp_sum(a3);
            if (lane == 0) {
                attn2[m][pass * 4 + 0] = a0 + qbs[pass * 4 + 0];
                attn2[m][pass * 4 + 1] = a1 + qbs[pass * 4 + 1];
                attn2[m][pass * 4 + 2] = a2 + qbs[pass * 4 + 2];
                attn2[m][pass * 4 + 3] = a3 + qbs[pass * 4 + 3];
            }
        }
    }
    __syncthreads();

    // softmax over m per head (warps 0..7)
    if (t < 256) {
        int h = w;
        float v0 = attn2[lane][h], v1 = attn2[lane + 32][h], v2 = attn2[lane + 64][h];
        float mx = warp_max(fmaxf(v0, fmaxf(v1, v2)));
        v0 = expf(v0 - mx); v1 = expf(v1 - mx); v2 = expf(v2 - mx);
        float inv = 1.0f / warp_sum(v0 + v1 + v2);
        attn2[lane][h] = v0 * inv; attn2[lane + 32][h] = v1 * inv; attn2[lane + 64][h] = v2 * inv;
    }
    __syncthreads();

    // tctx[h, d=t] = sum_m attn[m][h] * text[m][d]
    float acc[8] = {};
#pragma unroll 4
    for (int m = 0; m < kM; m++) {
        float tv = st[m * kD + t];
        float4 a0 = *(const float4*)&attn2[m][0];
        float4 a1 = *(const float4*)&attn2[m][4];
        acc[0] += a0.x * tv; acc[1] += a0.y * tv; acc[2] += a0.z * tv; acc[3] += a0.w * tv;
        acc[4] += a1.x * tv; acc[5] += a1.y * tv; acc[6] += a1.z * tv; acc[7] += a1.w * tv;
    }
    float* tb = g_tctx + (size_t)b * kH * kD + t;
#pragma unroll
    for (int h = 0; h < kH; h++) tb[(size_t)h * kD] = acc[h];
}

// ----- copy corrected to (unaligned) d_out, normalize into g_negs, pos_sim ----
__global__ void k_cn_pos(float* __restrict__ out_corr) {
    int b = blockIdx.x, t = threadIdx.x;  // 256
    const float* x = g_corr + (size_t)b * kD;
    const float* vnb = g_vn + (size_t)b * kD;
    float ss = 0.f, dt = 0.f;
    for (int i = t; i < kD; i += 256) {
        float v = x[i];
        out_corr[(size_t)b * kD + i] = v;
        ss += v * v; dt += vnb[i] * v;
    }
    __shared__ float rs[8], rd[8];
    ss = warp_sum(ss); dt = warp_sum(dt);
    if ((t & 31) == 0) { rs[t >> 5] = ss; rd[t >> 5] = dt; }
    __syncthreads();
    if (t < 32) {
        float s2 = (t < 8) ? rs[t] : 0.f;
        float d2 = (t < 8) ? rd[t] : 0.f;
        s2 = warp_sum(s2); d2 = warp_sum(d2);
        if (t == 0) { float inv = 1.0f / fmaxf(sqrtf(s2), kEps); rs[0] = inv; g_pos[b] = d2 * inv; }
    }
    __syncthreads();
    float inv = rs[0];
    for (int i = t; i < kD; i += 256) g_negs[(size_t)b * kD + i] = x[i] * inv;
}

// ----- normalize text_memory rows 512:1024 into g_negs[512:1024] --------------
__global__ void k_negs_mem(const float* __restrict__ tmem) {
    int j = blockIdx.x, t = threadIdx.x;  // 512 blocks × 128 threads
    const float* x = tmem + (size_t)(kB + j) * kD;
    float* out = g_negs + (size_t)(kB + j) * kD;
    float ss = 0.f;
    for (int i = t; i < kD; i += 128) { float v = x[i]; ss += v * v; }
    __shared__ float red[4];
    ss = warp_sum(ss);
    if ((t & 31) == 0) red[t >> 5] = ss;
    __syncthreads();
    float tot = red[0] + red[1] + red[2] + red[3];
    float inv = 1.0f / fmaxf(sqrtf(tot), kEps);
    for (int i = t; i < kD; i += 128) out[i] = x[i] * inv;
}

// ----- warp-per-b top-5 (cn sims count twice) + loss term ---------------------
__device__ __forceinline__ void ins5(float (&t5)[5], float v) {
    if (v > t5[4]) {
        t5[4] = v;
        if (t5[4] > t5[3]) { float tm = t5[3]; t5[3] = t5[4]; t5[4] = tm; }
        if (t5[3] > t5[2]) { float tm = t5[2]; t5[2] = t5[3]; t5[3] = tm; }
        if (t5[2] > t5[1]) { float tm = t5[1]; t5[1] = t5[2]; t5[2] = tm; }
        if (t5[1] > t5[0]) { float tm = t5[0]; t5[0] = t5[1]; t5[1] = tm; }
    }
}
__global__ void __launch_bounds__(512)
k_loss(const float* __restrict__ tpl, const float* __restrict__ tnl) {
    int b = blockIdx.x * 16 + (threadIdx.x >> 5);
    int lane = threadIdx.x & 31;
    const float* ns = g_nsims + (size_t)b * kNegC;
    float t5[5] = {-1e30f, -1e30f, -1e30f, -1e30f, -1e30f};
    for (int i = lane; i < 512; i += 32) {      // cn sims: multiplicity 2
        float v = ns[i];
        ins5(t5, v); ins5(t5, v);
    }
    for (int i = 512 + lane; i < 1024; i += 32) // mem sims
        ins5(t5, ns[i]);

    float tau_n = expf(tnl[0]);
    int ptr = 0;
    float neg = 0.f;
#pragma unroll
    for (int r = 0; r < 5; r++) {
        float mine = (ptr == 0) ? t5[0] : (ptr == 1) ? t5[1] : (ptr == 2) ? t5[2]
                   : (ptr == 3) ? t5[3] : (ptr == 4) ? t5[4] : -1e30f;
        float mx = warp_max(mine);
        unsigned bal = __ballot_sync(0xffffffffu, mine == mx);
        if (lane == (__ffs(bal) - 1)) ptr++;
        neg += expf(mx / tau_n);
    }
    if (lane == 0) {
        float tau_p = expf(tpl[0]);
        float pos = expf(g_pos[b] / tau_p);
        g_lossb[b] = logf(pos / (pos + neg + 1e-8f));
    }
}

__global__ void k_final(float* __restrict__ out) {
    int t = threadIdx.x;  // 512
    float v = g_lossb[t];
    __shared__ float red[16];
    v = warp_sum(v);
    if ((t & 31) == 0) red[t >> 5] = v;
    __syncthreads();
    if (t < 32) {
        float s = (t < 16) ? red[t] : 0.f;
        s = warp_sum(s);
        if (t == 0) out[0] = -s / (float)kB;
    }
}

// ---------------------------------------------------------------------------
extern "C" void kernel_launch(void* const* d_in, const int* in_sizes, int n_in,
                              void* d_out, int out_size) {
    const float* vis  = (const float*)d_in[0];
    const float* text = (const float*)d_in[1];
    const float* ipw  = (const float*)d_in[2];
    const float* ipb  = (const float*)d_in[3];
    const float* opw  = (const float*)d_in[4];
    const float* opb  = (const float*)d_in[5];
    const float* tmem = (const float*)d_in[6];
    const float* tpl  = (const float*)d_in[7];
    const float* tnl  = (const float*)d_in[8];

    float* out      = (float*)d_out;
    float* out_corr = out + 1;
    float* out_cs   = out + 1 + kB * kD;

    float *p_q, *p_vn, *p_tctx, *p_ctx, *p_corr, *p_negs, *p_nsims;
    cudaGetSymbolAddress((void**)&p_q,     g_q);
    cudaGetSymbolAddress((void**)&p_vn,    g_vn);
    cudaGetSymbolAddress((void**)&p_tctx,  g_tctx);
    cudaGetSymbolAddress((void**)&p_ctx,   g_ctx);
    cudaGetSymbolAddress((void**)&p_corr,  g_corr);
    cudaGetSymbolAddress((void**)&p_negs,  g_negs);
    cudaGetSymbolAddress((void**)&p_nsims, g_nsims);

    const int fusedSmem = (kM * kD + kH * kD + kD) * (int)sizeof(float);   // 215040 B
    cudaFuncSetAttribute(k_fused, cudaFuncAttributeMaxDynamicSharedMemorySize, fusedSmem);

    // 1. normalize vis
    k_norm_vis<<<kB, 256>>>(vis);
    // 2. normalize memory negatives (independent)
    k_negs_mem<<<kB, 128>>>(tmem);
    // 3. q = vis @ Wq^T + bq
    k_gemm_nt<<<dim3(kD / 64, kB / 64, 1), 256>>>(vis, kD, 0, ipw, kD, 0, ipb, 0,
                                                  p_q, kD, 0, kD);
    // 4. qt = (1/8) q_h @ Wk_h   (per head)
    k_qt_kernel<<<dim3(kD / 64, kB / 64, kH), 256>>>(ipw + (size_t)kD * kD);
    // 5. fused: qb + sims + clustering + logits + softmax + tctx
    k_fused<<<kB, 512, fusedSmem>>>(text, ipb + kD, out_cs);
    // 6. ctx_h = tctx_h @ Wv_h^T + bv_h   (block-diagonal, grid.z = head)
    k_gemm_nt<<<dim3(1, kB / 64, kH), 256>>>(p_tctx, kH * kD, kD,
                                             ipw + 2 * (size_t)kD * kD, kD, kDH * kD,
                                             ipb + 2 * kD, kDH,
                                             p_ctx, kD, kDH, kD);
    // 7. corrected = ctx @ Wo^T + bo  -> aligned scratch
    k_gemm_nt<<<dim3(kD / 64, kB / 64, 1), 256>>>(p_ctx, kD, 0, opw, kD, 0, opb, 0,
                                                  p_corr, kD, 0, kD);
    // 8. copy to d_out (+1, unaligned) + normalize into g_negs[0:512] + pos_sim
    k_cn_pos<<<kB, 256>>>(out_corr);
    // 9. neg_sims = vn @ negs^T   (512 x 1024 x 512)
    k_gemm_nt<<<dim3(kNegC / 64, kB / 64, 1), 256>>>(p_vn, kD, 0, p_negs, kD, 0,
                                                     nullptr, 0, p_nsims, kNegC, 0, kD);
    // 10. top-5 (with multiplicity) + per-row loss
    k_loss<<<kB / 16, 512>>>(tpl, tnl);
    // 11. mean reduce -> loss scalar
    k_final<<<1, 512>>>(out);
}

// round 4
// speedup vs baseline: 1.2490x; 1.1136x over previous
#include <cuda_runtime.h>

// ---------------------------------------------------------------------------
// DiscriminativeClueCorrection — fp32, restructured attention, streaming fused.
// Output layout (float32): [loss(1)] [corrected(512*512)] [cluster_scores(512*3)]
// ---------------------------------------------------------------------------

constexpr int kB    = 512;
constexpr int kM    = 96;
constexpr int kD    = 512;
constexpr int kH    = 8;
constexpr int kDH   = 64;
constexpr int kNC   = 3;
constexpr int kNegC = 1024;         // unique negative columns (cn ×512 + mem ×512)
constexpr float kEps = 1e-8f;

// ----- device scratch --------------------------------------------------------
__device__ float g_vn   [kB * kD];
__device__ float g_q    [kB * kD];
__device__ float g_qt   [kB * kH * kD];   // per-b transformed key weights (×1/8)
__device__ float g_tctx [kB * kH * kD];
__device__ float g_ctx  [kB * kD];
__device__ float g_corr [kB * kD];
__device__ float g_pos  [kB];
__device__ float g_negs [kNegC * kD];
__device__ float g_nsims[kB * kNegC];
__device__ float g_lossb[kB];

__device__ __forceinline__ float warp_sum(float v) {
#pragma unroll
    for (int o = 16; o > 0; o >>= 1) v += __shfl_xor_sync(0xffffffffu, v, o);
    return v;
}
__device__ __forceinline__ float warp_max(float v) {
#pragma unroll
    for (int o = 16; o > 0; o >>= 1) v = fmaxf(v, __shfl_xor_sync(0xffffffffu, v, o));
    return v;
}

// ----- f32x2 packed helpers ---------------------------------------------------
__device__ __forceinline__ unsigned long long dup2(float v) {
    unsigned long long r;
    asm("mov.b64 %0, {%1,%1};" : "=l"(r) : "f"(v));
    return r;
}
__device__ __forceinline__ void fma2(unsigned long long& acc, unsigned long long a,
                                     unsigned long long b) {
    asm("fma.rn.f32x2 %0, %1, %2, %0;" : "+l"(acc) : "l"(a), "l"(b));
}
__device__ __forceinline__ float2 unpack2(unsigned long long v) {
    float2 f;
    asm("mov.b64 {%0,%1}, %2;" : "=f"(f.x), "=f"(f.y) : "l"(v));
    return f;
}

// ----- normalize vis_global rows ----------------------------------------------
__global__ void k_norm_vis(const float* __restrict__ vis) {
    int b = blockIdx.x, t = threadIdx.x;                 // 256 threads
    const float* x = vis + (size_t)b * kD;
    float ss = 0.f;
    for (int i = t; i < kD; i += 256) { float v = x[i]; ss += v * v; }
    __shared__ float red[8];
    ss = warp_sum(ss);
    if ((t & 31) == 0) red[t >> 5] = ss;
    __syncthreads();
    if (t < 32) {
        float v = (t < 8) ? red[t] : 0.f;
        v = warp_sum(v);
        if (t == 0) red[0] = v;
    }
    __syncthreads();
    float inv = 1.0f / fmaxf(sqrtf(red[0]), kEps);
    for (int i = t; i < kD; i += 256) g_vn[(size_t)b * kD + i] = x[i] * inv;
}

// ----- NT GEMM with FFMA2: C = A(MxK) @ B(NxK)^T + bias, 64x64 tile, BK=16 ----
__global__ void __launch_bounds__(256)
k_gemm_nt(const float* __restrict__ A, int lda, int sAz,
          const float* __restrict__ Bm, int ldb, int sBz,
          const float* __restrict__ bias, int sBiasz,
          float* __restrict__ C, int ldc, int sCz, int K) {
    A  += (size_t)blockIdx.z * sAz + (size_t)blockIdx.y * 64 * lda;
    Bm += (size_t)blockIdx.z * sBz + (size_t)blockIdx.x * 64 * ldb;
    C  += (size_t)blockIdx.z * sCz + (size_t)blockIdx.y * 64 * ldc + blockIdx.x * 64;
    int biasOff = blockIdx.z * sBiasz + blockIdx.x * 64;

    __shared__ __align__(16) float As2[16][128];   // A duplicated: [k][2r],[k][2r+1]
    __shared__ __align__(16) float Bs[16][64];
    int tid = threadIdx.x;
    int tx = tid & 15, ty = tid >> 4;
    int lr = tid >> 2, lk = (tid & 3) << 2;

    const float* Aload = A + (size_t)lr * lda + lk;
    const float* Bload = Bm + (size_t)lr * ldb + lk;
    float4 a4 = *(const float4*)Aload;
    float4 b4 = *(const float4*)Bload;

    unsigned long long acc[4][2] = {};
    for (int k0 = 0; k0 < K; k0 += 16) {
        *(unsigned long long*)&As2[lk + 0][2 * lr] = dup2(a4.x);
        *(unsigned long long*)&As2[lk + 1][2 * lr] = dup2(a4.y);
        *(unsigned long long*)&As2[lk + 2][2 * lr] = dup2(a4.z);
        *(unsigned long long*)&As2[lk + 3][2 * lr] = dup2(a4.w);
        Bs[lk + 0][lr] = b4.x; Bs[lk + 1][lr] = b4.y;
        Bs[lk + 2][lr] = b4.z; Bs[lk + 3][lr] = b4.w;
        __syncthreads();
        if (k0 + 16 < K) {
            a4 = *(const float4*)(Aload + k0 + 16);
            b4 = *(const float4*)(Bload + k0 + 16);
        }
#pragma unroll
        for (int k = 0; k < 16; k++) {
            ulonglong2 ap0 = *(const ulonglong2*)&As2[k][ty * 8];
            ulonglong2 ap1 = *(const ulonglong2*)&As2[k][ty * 8 + 4];
            ulonglong2 bp  = *(const ulonglong2*)&Bs[k][tx * 4];
            fma2(acc[0][0], ap0.x, bp.x); fma2(acc[0][1], ap0.x, bp.y);
            fma2(acc[1][0], ap0.y, bp.x); fma2(acc[1][1], ap0.y, bp.y);
            fma2(acc[2][0], ap1.x, bp.x); fma2(acc[2][1], ap1.x, bp.y);
            fma2(acc[3][0], ap1.y, bp.x); fma2(acc[3][1], ap1.y, bp.y);
        }
        __syncthreads();
    }
#pragma unroll
    for (int i = 0; i < 4; i++) {
        int row = ty * 4 + i;
        int col = tx * 4;
        float2 c0 = unpack2(acc[i][0]);
        float2 c1 = unpack2(acc[i][1]);
        float4 v = make_float4(c0.x, c0.y, c1.x, c1.y);
        if (bias) {
            v.x += bias[biasOff + col + 0]; v.y += bias[biasOff + col + 1];
            v.z += bias[biasOff + col + 2]; v.w += bias[biasOff + col + 3];
        }
        *(float4*)&C[(size_t)row * ldc + col] = v;
    }
}

// ----- qt[b,h,d] = (1/8) * sum_dh q[b,h,dh] * Wk[h*64+dh, d]  (NN, K=64) ------
__global__ void __launch_bounds__(256)
k_qt_kernel(const float* __restrict__ wk) {
    int h = blockIdx.z, b0 = blockIdx.y * 64, d0 = blockIdx.x * 64;
    __shared__ __align__(16) float Qs2[64][128];   // [dh][2b] duplicated
    __shared__ __align__(16) float Ws[64][64];     // [dh][d], pre-scaled by 1/8
    int tid = threadIdx.x;

    {
        int lr = tid >> 2, lk = (tid & 3) << 2;
        const float* qrow = g_q + (size_t)(b0 + lr) * kD + h * kDH;
#pragma unroll
        for (int c = 0; c < 4; c++) {
            float4 v = *(const float4*)(qrow + lk + c * 16);
            int cc = lk + c * 16;
            *(unsigned long long*)&Qs2[cc + 0][2 * lr] = dup2(v.x);
            *(unsigned long long*)&Qs2[cc + 1][2 * lr] = dup2(v.y);
            *(unsigned long long*)&Qs2[cc + 2][2 * lr] = dup2(v.z);
            *(unsigned long long*)&Qs2[cc + 3][2 * lr] = dup2(v.w);
        }
    }
    {
        int wr = tid >> 2, wc = (tid & 3) << 2;
        const float* wrow = wk + (size_t)(h * kDH + wr) * kD + d0;
#pragma unroll
        for (int c = 0; c < 4; c++) {
            float4 v = *(const float4*)(wrow + wc + c * 16);
            v.x *= 0.125f; v.y *= 0.125f; v.z *= 0.125f; v.w *= 0.125f;
            *(float4*)&Ws[wr][wc + c * 16] = v;
        }
    }
    __syncthreads();

    int tx = tid & 15, ty = tid >> 4;
    unsigned long long acc[4][2] = {};
#pragma unroll 8
    for (int k = 0; k < 64; k++) {
        ulonglong2 ap0 = *(const ulonglong2*)&Qs2[k][ty * 8];
        ulonglong2 ap1 = *(const ulonglong2*)&Qs2[k][ty * 8 + 4];
        ulonglong2 bp  = *(const ulonglong2*)&Ws[k][tx * 4];
        fma2(acc[0][0], ap0.x, bp.x); fma2(acc[0][1], ap0.x, bp.y);
        fma2(acc[1][0], ap0.y, bp.x); fma2(acc[1][1], ap0.y, bp.y);
        fma2(acc[2][0], ap1.x, bp.x); fma2(acc[2][1], ap1.x, bp.y);
        fma2(acc[3][0], ap1.y, bp.x); fma2(acc[3][1], ap1.y, bp.y);
    }
#pragma unroll
    for (int i = 0; i < 4; i++) {
        float2 c0 = unpack2(acc[i][0]);
        float2 c1 = unpack2(acc[i][1]);
        float4 v = make_float4(c0.x, c0.y, c1.x, c1.y);
        *(float4*)&g_qt[(size_t)(b0 + ty * 4 + i) * (kH * kD) + (size_t)h * kD + d0 + tx * 4] = v;
    }
}

// ----- fused per-b: sims + sort/cluster + logits + softmax + tctx -------------
// 256 threads. qt[b] and vn[b] live in registers; text streamed from global
// twice (pass1: sims+logits, pass2: tctx). No dynamic smem.
__global__ void __launch_bounds__(256)
k_attn(const float* __restrict__ text, float* __restrict__ out_cs) {
    __shared__ float sims[128];
    __shared__ __align__(16) float attn2[kM][kH];   // logits, then attn
    int b = blockIdx.x, t = threadIdx.x;
    int w = t >> 5, lane = t & 31;                  // 8 warps

    // qt[b] (pre-scaled 1/8) into regs: lane owns float4s {lane+32j}
    float qa[kH][16];
    {
        const float4* qt4 = (const float4*)(g_qt + (size_t)b * kH * kD);
#pragma unroll
        for (int h = 0; h < kH; h++)
#pragma unroll
            for (int j = 0; j < 4; j++) {
                float4 v = qt4[h * 128 + lane + 32 * j];
                qa[h][j * 4 + 0] = v.x; qa[h][j * 4 + 1] = v.y;
                qa[h][j * 4 + 2] = v.z; qa[h][j * 4 + 3] = v.w;
            }
    }
    float vnr[16];
    {
        const float4* vn4 = (const float4*)(g_vn + (size_t)b * kD);
#pragma unroll
        for (int j = 0; j < 4; j++) {
            float4 v = vn4[lane + 32 * j];
            vnr[j * 4 + 0] = v.x; vnr[j * 4 + 1] = v.y;
            vnr[j * 4 + 2] = v.z; vnr[j * 4 + 3] = v.w;
        }
    }

    // ---- pass 1: sims[m] and logits[m][h]; warp handles m = w, w+8, ... -----
    const float4* trow = (const float4*)(text + (size_t)b * kM * kD);
    float4 pre[4];
    {
        const float4* r = trow + (size_t)w * 128;
#pragma unroll
        for (int j = 0; j < 4; j++) pre[j] = r[lane + 32 * j];
    }
    for (int m = w; m < kM; m += 8) {
        float tx[16];
#pragma unroll
        for (int j = 0; j < 4; j++) {
            tx[j * 4 + 0] = pre[j].x; tx[j * 4 + 1] = pre[j].y;
            tx[j * 4 + 2] = pre[j].z; tx[j * 4 + 3] = pre[j].w;
        }
        if (m + 8 < kM) {
            const float4* r = trow + (size_t)(m + 8) * 128;
#pragma unroll
            for (int j = 0; j < 4; j++) pre[j] = r[lane + 32 * j];
        }
        float dot = 0.f, ss = 0.f, a[kH] = {};
#pragma unroll
        for (int i = 0; i < 16; i++) {
            float tv = tx[i];
            dot += vnr[i] * tv; ss += tv * tv;
#pragma unroll
            for (int h = 0; h < kH; h++) a[h] += qa[h][i] * tv;
        }
        dot = warp_sum(dot); ss = warp_sum(ss);
#pragma unroll
        for (int h = 0; h < kH; h++) a[h] = warp_sum(a[h]);
        if (lane == 0) {
            sims[m] = dot / fmaxf(sqrtf(ss), kEps);
#pragma unroll
            for (int h = 0; h < kH; h++) attn2[m][h] = a[h];
        }
    }
    if (t >= kM && t < 128) sims[t] = -1e30f;
    __syncthreads();

    // ---- bitonic ascending sort of sims[128] --------------------------------
    for (int k = 2; k <= 128; k <<= 1)
        for (int j = k >> 1; j > 0; j >>= 1) {
            if (t < 128) {
                int ixj = t ^ j;
                if (ixj > t) {
                    float a = sims[t], c = sims[ixj];
                    bool up = ((t & k) == 0);
                    if ((a > c) == up) { sims[t] = c; sims[ixj] = a; }
                }
            }
            __syncthreads();
        }

    // ---- cluster stats on descending groups of 32 (warps 0..2) --------------
    if (t < kM) {
        float v = sims[127 - t];
        float mean = warp_sum(v) * (1.0f / 32.0f);
        float dv = v - mean;
        float var = warp_sum(dv * dv) * (1.0f / 31.0f);
        if (lane == 0) out_cs[b * kNC + (t >> 5)] = mean / (sqrtf(var) + 1e-6f);
    }

    // ---- softmax over m per head (warp w = head) -----------------------------
    {
        int h = w;
        float v0 = attn2[lane][h], v1 = attn2[lane + 32][h], v2 = attn2[lane + 64][h];
        float mx = warp_max(fmaxf(v0, fmaxf(v1, v2)));
        v0 = expf(v0 - mx); v1 = expf(v1 - mx); v2 = expf(v2 - mx);
        float inv = 1.0f / warp_sum(v0 + v1 + v2);
        attn2[lane][h] = v0 * inv; attn2[lane + 32][h] = v1 * inv; attn2[lane + 64][h] = v2 * inv;
    }
    __syncthreads();

    // ---- pass 2: tctx[h][d] = sum_m attn[m][h]*text[m][d]; thread owns float2 d=2t
    float2 acc[kH] = {};
    const float2* rb = (const float2*)(text + (size_t)b * kM * kD);
#pragma unroll 8
    for (int m = 0; m < kM; m++) {
        float2 tv = rb[(size_t)m * 256 + t];
        float4 a0 = *(const float4*)&attn2[m][0];
        float4 a1 = *(const float4*)&attn2[m][4];
        acc[0].x += a0.x * tv.x; acc[0].y += a0.x * tv.y;
        acc[1].x += a0.y * tv.x; acc[1].y += a0.y * tv.y;
        acc[2].x += a0.z * tv.x; acc[2].y += a0.z * tv.y;
        acc[3].x += a0.w * tv.x; acc[3].y += a0.w * tv.y;
        acc[4].x += a1.x * tv.x; acc[4].y += a1.x * tv.y;
        acc[5].x += a1.y * tv.x; acc[5].y += a1.y * tv.y;
        acc[6].x += a1.z * tv.x; acc[6].y += a1.z * tv.y;
        acc[7].x += a1.w * tv.x; acc[7].y += a1.w * tv.y;
    }
    float* tb = g_tctx + (size_t)b * kH * kD;
#pragma unroll
    for (int h = 0; h < kH; h++) ((float2*)(tb + h * kD))[t] = acc[h];
}

// ----- copy corrected to (unaligned) d_out, normalize into g_negs, pos_sim ----
__global__ void k_cn_pos(float* __restrict__ out_corr) {
    int b = blockIdx.x, t = threadIdx.x;  // 256
    const float* x = g_corr + (size_t)b * kD;
    const float* vnb = g_vn + (size_t)b * kD;
    float ss = 0.f, dt = 0.f;
    for (int i = t; i < kD; i += 256) {
        float v = x[i];
        out_corr[(size_t)b * kD + i] = v;
        ss += v * v; dt += vnb[i] * v;
    }
    __shared__ float rs[8], rd[8];
    ss = warp_sum(ss); dt = warp_sum(dt);
    if ((t & 31) == 0) { rs[t >> 5] = ss; rd[t >> 5] = dt; }
    __syncthreads();
    if (t < 32) {
        float s2 = (t < 8) ? rs[t] : 0.f;
        float d2 = (t < 8) ? rd[t] : 0.f;
        s2 = warp_sum(s2); d2 = warp_sum(d2);
        if (t == 0) { float inv = 1.0f / fmaxf(sqrtf(s2), kEps); rs[0] = inv; g_pos[b] = d2 * inv; }
    }
    __syncthreads();
    float inv = rs[0];
    for (int i = t; i < kD; i += 256) g_negs[(size_t)b * kD + i] = x[i] * inv;
}

// ----- normalize text_memory rows 512:1024 into g_negs[512:1024] --------------
__global__ void k_negs_mem(const float* __restrict__ tmem) {
    int j = blockIdx.x, t = threadIdx.x;  // 512 blocks × 128 threads
    const float* x = tmem + (size_t)(kB + j) * kD;
    float* out = g_negs + (size_t)(kB + j) * kD;
    float ss = 0.f;
    for (int i = t; i < kD; i += 128) { float v = x[i]; ss += v * v; }
    __shared__ float red[4];
    ss = warp_sum(ss);
    if ((t & 31) == 0) red[t >> 5] = ss;
    __syncthreads();
    float tot = red[0] + red[1] + red[2] + red[3];
    float inv = 1.0f / fmaxf(sqrtf(tot), kEps);
    for (int i = t; i < kD; i += 128) out[i] = x[i] * inv;
}

// ----- warp-per-b top-5 (cn sims count twice) + loss term ---------------------
__device__ __forceinline__ void ins5(float (&t5)[5], float v) {
    if (v > t5[4]) {
        t5[4] = v;
        if (t5[4] > t5[3]) { float tm = t5[3]; t5[3] = t5[4]; t5[4] = tm; }
        if (t5[3] > t5[2]) { float tm = t5[2]; t5[2] = t5[3]; t5[3] = tm; }
        if (t5[2] > t5[1]) { float tm = t5[1]; t5[1] = t5[2]; t5[2] = tm; }
        if (t5[1] > t5[0]) { float tm = t5[0]; t5[0] = t5[1]; t5[1] = tm; }
    }
}
__global__ void __launch_bounds__(512)
k_loss(const float* __restrict__ tpl, const float* __restrict__ tnl) {
    int b = blockIdx.x * 16 + (threadIdx.x >> 5);
    int lane = threadIdx.x & 31;
    const float* ns = g_nsims + (size_t)b * kNegC;
    float t5[5] = {-1e30f, -1e30f, -1e30f, -1e30f, -1e30f};
    for (int i = lane; i < 512; i += 32) {      // cn sims: multiplicity 2
        float v = ns[i];
        ins5(t5, v); ins5(t5, v);
    }
    for (int i = 512 + lane; i < 1024; i += 32) // mem sims
        ins5(t5, ns[i]);

    float tau_n = expf(tnl[0]);
    int ptr = 0;
    float neg = 0.f;
#pragma unroll
    for (int r = 0; r < 5; r++) {
        float mine = (ptr == 0) ? t5[0] : (ptr == 1) ? t5[1] : (ptr == 2) ? t5[2]
                   : (ptr == 3) ? t5[3] : (ptr == 4) ? t5[4] : -1e30f;
        float mx = warp_max(mine);
        unsigned bal = __ballot_sync(0xffffffffu, mine == mx);
        if (lane == (__ffs(bal) - 1)) ptr++;
        neg += expf(mx / tau_n);
    }
    if (lane == 0) {
        float tau_p = expf(tpl[0]);
        float pos = expf(g_pos[b] / tau_p);
        g_lossb[b] = logf(pos / (pos + neg + 1e-8f));
    }
}

__global__ void k_final(float* __restrict__ out) {
    int t = threadIdx.x;  // 512
    float v = g_lossb[t];
    __shared__ float red[16];
    v = warp_sum(v);
    if ((t & 31) == 0) red[t >> 5] = v;
    __syncthreads();
    if (t < 32) {
        float s = (t < 16) ? red[t] : 0.f;
        s = warp_sum(s);
        if (t == 0) out[0] = -s / (float)kB;
    }
}

// ---------------------------------------------------------------------------
extern "C" void kernel_launch(void* const* d_in, const int* in_sizes, int n_in,
                              void* d_out, int out_size) {
    const float* vis  = (const float*)d_in[0];
    const float* text = (const float*)d_in[1];
    const float* ipw  = (const float*)d_in[2];
    const float* ipb  = (const float*)d_in[3];
    const float* opw  = (const float*)d_in[4];
    const float* opb  = (const float*)d_in[5];
    const float* tmem = (const float*)d_in[6];
    const float* tpl  = (const float*)d_in[7];
    const float* tnl  = (const float*)d_in[8];

    float* out      = (float*)d_out;
    float* out_corr = out + 1;
    float* out_cs   = out + 1 + kB * kD;

    float *p_q, *p_vn, *p_tctx, *p_ctx, *p_corr, *p_negs, *p_nsims;
    cudaGetSymbolAddress((void**)&p_q,     g_q);
    cudaGetSymbolAddress((void**)&p_vn,    g_vn);
    cudaGetSymbolAddress((void**)&p_tctx,  g_tctx);
    cudaGetSymbolAddress((void**)&p_ctx,   g_ctx);
    cudaGetSymbolAddress((void**)&p_corr,  g_corr);
    cudaGetSymbolAddress((void**)&p_negs,  g_negs);
    cudaGetSymbolAddress((void**)&p_nsims, g_nsims);

    // 1. normalize vis
    k_norm_vis<<<kB, 256>>>(vis);
    // 2. normalize memory negatives (independent)
    k_negs_mem<<<kB, 128>>>(tmem);
    // 3. q = vis @ Wq^T + bq
    k_gemm_nt<<<dim3(kD / 64, kB / 64, 1), 256>>>(vis, kD, 0, ipw, kD, 0, ipb, 0,
                                                  p_q, kD, 0, kD);
    // 4. qt = (1/8) q_h @ Wk_h   (per head)
    k_qt_kernel<<<dim3(kD / 64, kB / 64, kH), 256>>>(ipw + (size_t)kD * kD);
    // 5. fused: sims + clustering + logits + softmax + tctx (streaming, no smem staging)
    k_attn<<<kB, 256>>>(text, out_cs);
    // 6. ctx_h = tctx_h @ Wv_h^T + bv_h   (block-diagonal, grid.z = head)
    k_gemm_nt<<<dim3(1, kB / 64, kH), 256>>>(p_tctx, kH * kD, kD,
                                             ipw + 2 * (size_t)kD * kD, kD, kDH * kD,
                                             ipb + 2 * kD, kDH,
                                             p_ctx, kD, kDH, kD);
    // 7. corrected = ctx @ Wo^T + bo  -> aligned scratch
    k_gemm_nt<<<dim3(kD / 64, kB / 64, 1), 256>>>(p_ctx, kD, 0, opw, kD, 0, opb, 0,
                                                  p_corr, kD, 0, kD);
    // 8. copy to d_out (+1, unaligned) + normalize into g_negs[0:512] + pos_sim
    k_cn_pos<<<kB, 256>>>(out_corr);
    // 9. neg_sims = vn @ negs^T   (512 x 1024 x 512)
    k_gemm_nt<<<dim3(kNegC / 64, kB / 64, 1), 256>>>(p_vn, kD, 0, p_negs, kD, 0,
                                                     nullptr, 0, p_nsims, kNegC, 0, kD);
    // 10. top-5 (with multiplicity) + per-row loss
    k_loss<<<kB / 16, 512>>>(tpl, tnl);
    // 11. mean reduce -> loss scalar
    k_final<<<1, 512>>>(out);
}